// round 4
// baseline (speedup 1.0000x reference)
#include <cuda_runtime.h>
#include <math_constants.h>

// EMDLoss (Sinkhorn, eps=0.005, 50 iters), B=8, N=2048, dim=3.
// Morton-sorted point sets (survivor clustering) + factored cost in log2
// domain + truncated online log2-sum-exp with warp-shared running max.

#define BB 8
#define NN 2048

static __device__ float4 d_P4[BB * NN];   // sorted (x,y,z, |p|^2*S2)
static __device__ float4 d_Q4[BB * NN];
static __device__ float  d_f[BB * NN];
static __device__ float  d_g[BB * NN];
static __device__ float  d_partials[512];

__device__ __forceinline__ float ex2f_(float x) {
    float r; asm("ex2.approx.f32 %0, %1;" : "=f"(r) : "f"(x)); return r;
}
__device__ __forceinline__ float lg2f_(float x) {
    float r; asm("lg2.approx.f32 %0, %1;" : "=f"(r) : "f"(x)); return r;
}

#define S2F      288.5390081777927f      // 1/(eps*ln2)
#define S2X2     577.0780163555854f      // 2/(eps*ln2)
#define EPSLN2   0.0034657359027997f     // eps*ln2
#define EPSLOGMU (-0.03812309493079699f) // eps * (-ln N)
#define TT       25.0f                   // half-update truncation (log2)
#define TTL      33.0f                   // loss truncation (log2)

// ---------------------------------------------------------------------------
// Morton-sort each (batch, set) with an in-smem bitonic sort; write sorted
// float4 (x,y,z,|p|^2*S2) and zero the potential. Key = morton15 << 11 | idx.
__global__ void __launch_bounds__(256) prep_sort_kernel(
    const float* __restrict__ preds, const float* __restrict__ gts) {
    int blk = blockIdx.x;
    int b = blk >> 1;
    int set = blk & 1;
    const float* src = set ? gts : preds;
    float4* dst = set ? d_Q4 : d_P4;
    float*  pot = set ? d_g  : d_f;
    int off = b * NN;

    __shared__ unsigned skey[NN];

    for (int i = threadIdx.x; i < NN; i += 256) {
        const float* p = src + (off + i) * 3;
        float x = p[0], y = p[1], z = p[2];
        int ux = (int)floorf((x + 4.f) * 4.f); ux = min(31, max(0, ux));
        int uy = (int)floorf((y + 4.f) * 4.f); uy = min(31, max(0, uy));
        int uz = (int)floorf((z + 4.f) * 4.f); uz = min(31, max(0, uz));
        unsigned key = 0;
#pragma unroll
        for (int bit = 0; bit < 5; ++bit) {
            key |= (((unsigned)ux >> bit) & 1u) << (3 * bit + 2);
            key |= (((unsigned)uy >> bit) & 1u) << (3 * bit + 1);
            key |= (((unsigned)uz >> bit) & 1u) << (3 * bit + 0);
        }
        skey[i] = (key << 11) | (unsigned)i;
    }
    __syncthreads();

    for (int k = 2; k <= NN; k <<= 1) {
        for (int j = k >> 1; j > 0; j >>= 1) {
            for (int i = threadIdx.x; i < NN; i += 256) {
                int l = i ^ j;
                if (l > i) {
                    unsigned a = skey[i], c = skey[l];
                    bool up = ((i & k) == 0);
                    if ((a > c) == up) { skey[i] = c; skey[l] = a; }
                }
            }
            __syncthreads();
        }
    }

    for (int i = threadIdx.x; i < NN; i += 256) {
        int si = (int)(skey[i] & 2047u);
        const float* p = src + (off + si) * 3;
        float x = p[0], y = p[1], z = p[2];
        dst[off + i] = make_float4(x, y, z, (x * x + y * y + z * z) * S2F);
        pot[off + i] = 0.f;
    }
}

// ---------------------------------------------------------------------------
#define MERGEROW(m, s, off)                                         \
    {                                                               \
        float mo = __shfl_xor_sync(0xffffffffu, m, off);            \
        float so = __shfl_xor_sync(0xffffffffu, s, off);            \
        float mn = fmaxf(m, mo);                                    \
        s = fmaf(so, ex2f_(mo - mn), s * ex2f_(m - mn));            \
        m = mn;                                                     \
    }

// Per-row triggered update. m is warp-uniform; shfl tree only on new max.
#define ROWUPD(m, s, mt, a, e)                                      \
    if (__any_sync(0xffffffffu, (e) > 0.f)) {                       \
        if (__any_sync(0xffffffffu, (a) > (m))) {                   \
            float c = fmaxf(m, a);                                  \
            c = fmaxf(c, __shfl_xor_sync(0xffffffffu, c, 16));      \
            c = fmaxf(c, __shfl_xor_sync(0xffffffffu, c, 8));       \
            c = fmaxf(c, __shfl_xor_sync(0xffffffffu, c, 4));       \
            c = fmaxf(c, __shfl_xor_sync(0xffffffffu, c, 2));       \
            c = fmaxf(c, __shfl_xor_sync(0xffffffffu, c, 1));       \
            s = fmaf(s, ex2f_(m - c), ex2f_((a) - c));              \
            m = c; mt = c - TT;                                     \
        } else {                                                    \
            s += ex2f_((a) - m);   /* underflow = truncation */     \
        }                                                           \
    }

// One Sinkhorn half-update. dir=0: update f (rows=preds, table=gts/g).
__global__ void __launch_bounds__(256) half_kernel(int dir) {
    int blk = blockIdx.x;
    int b = blk >> 6;
    int chunk = blk & 63;

    const float4* R4  = dir ? d_Q4 : d_P4;
    const float4* D4  = dir ? d_P4 : d_Q4;
    const float*  pin = dir ? d_f  : d_g;
    float*        pout = dir ? d_g : d_f;

    __shared__ float4 tbl[NN];
    {
        const float4* Db = D4 + b * NN;
        const float*  pb = pin + b * NN;
        for (int j = threadIdx.x; j < NN; j += 256) {
            float4 q = Db[j];
            float4 t;
            t.x = q.x * S2X2;
            t.y = q.y * S2X2;
            t.z = q.z * S2X2;
            t.w = fmaf(pb[j], S2F, -q.w);   // pot_j*S2 - |q|^2*S2
            tbl[j] = t;
        }
    }
    __syncthreads();

    int warp = threadIdx.x >> 5;
    int lane = threadIdx.x & 31;
    int row0 = b * NN + chunk * 32 + warp * 4;

    float4 r0 = R4[row0 + 0];
    float4 r1 = R4[row0 + 1];
    float4 r2 = R4[row0 + 2];
    float4 r3 = R4[row0 + 3];

    const float NEGINF = -CUDART_INF_F;
    float m0 = NEGINF, m1 = NEGINF, m2 = NEGINF, m3 = NEGINF;
    float s0 = 0.f, s1 = 0.f, s2 = 0.f, s3 = 0.f;
    float mt0 = NEGINF, mt1 = NEGINF, mt2 = NEGINF, mt3 = NEGINF;

#pragma unroll 2
    for (int k = 0; k < 64; ++k) {
        float4 q = tbl[(k << 5) + lane];
        float a0 = fmaf(r0.x, q.x, fmaf(r0.y, q.y, fmaf(r0.z, q.z, q.w)));
        float a1 = fmaf(r1.x, q.x, fmaf(r1.y, q.y, fmaf(r1.z, q.z, q.w)));
        float a2 = fmaf(r2.x, q.x, fmaf(r2.y, q.y, fmaf(r2.z, q.z, q.w)));
        float a3 = fmaf(r3.x, q.x, fmaf(r3.y, q.y, fmaf(r3.z, q.z, q.w)));
        float e0 = a0 - mt0;
        float e1 = a1 - mt1;
        float e2 = a2 - mt2;
        float e3 = a3 - mt3;
        float emax = fmaxf(fmaxf(e0, e1), fmaxf(e2, e3));
        if (__any_sync(0xffffffffu, emax > 0.f)) {
            ROWUPD(m0, s0, mt0, a0, e0)
            ROWUPD(m1, s1, mt1, a1, e1)
            ROWUPD(m2, s2, mt2, a2, e2)
            ROWUPD(m3, s3, mt3, a3, e3)
        }
    }

#pragma unroll
    for (int off = 16; off; off >>= 1) {
        MERGEROW(m0, s0, off);
        MERGEROW(m1, s1, off);
        MERGEROW(m2, s2, off);
        MERGEROW(m3, s3, off);
    }

    if (lane == 0) {
        pout[row0 + 0] = fmaf(-EPSLN2, (-r0.w) + m0 + lg2f_(s0), EPSLOGMU);
        pout[row0 + 1] = fmaf(-EPSLN2, (-r1.w) + m1 + lg2f_(s1), EPSLOGMU);
        pout[row0 + 2] = fmaf(-EPSLN2, (-r2.w) + m2 + lg2f_(s2), EPSLOGMU);
        pout[row0 + 3] = fmaf(-EPSLN2, (-r3.w) + m3 + lg2f_(s3), EPSLOGMU);
    }
}

// ---------------------------------------------------------------------------
// Loss: part += P_ij * C_ij, truncated at arg = log2(P) < -TTL.
// e = arg + TTL; arg <= 0 always (row sums of P are 1/n).
#define LROW(fr, e, gj)                                             \
    if (__any_sync(0xffffffffu, (e) > 0.f)) {                       \
        float arg = (e) - TTL;                                      \
        float C = fmaf(-EPSLN2, arg, (fr) + (gj));                  \
        part = fmaf(ex2f_(arg), C, part);                           \
    }

__global__ void __launch_bounds__(256) loss_kernel() {
    int blk = blockIdx.x;
    int b = blk >> 6;
    int chunk = blk & 63;

    __shared__ float4 tbl[NN];
    __shared__ float  gg[NN];
    {
        const float4* Db = d_Q4 + b * NN;
        const float*  pb = d_g + b * NN;
        for (int j = threadIdx.x; j < NN; j += 256) {
            float4 q = Db[j];
            float gj = pb[j];
            float4 t;
            t.x = q.x * S2X2;
            t.y = q.y * S2X2;
            t.z = q.z * S2X2;
            t.w = fmaf(gj, S2F, -q.w);
            tbl[j] = t;
            gg[j] = gj;
        }
    }
    __syncthreads();

    int warp = threadIdx.x >> 5;
    int lane = threadIdx.x & 31;
    int row0 = b * NN + chunk * 32 + warp * 4;

    float4 r0 = d_P4[row0 + 0];
    float4 r1 = d_P4[row0 + 1];
    float4 r2 = d_P4[row0 + 2];
    float4 r3 = d_P4[row0 + 3];
    float fr0 = d_f[row0 + 0], fr1 = d_f[row0 + 1];
    float fr2 = d_f[row0 + 2], fr3 = d_f[row0 + 3];
    // ffT_i = f_i*S2 - pp_i*S2 + TTL, so e = a + ffT = arg + TTL
    float ffT0 = fmaf(fr0, S2F, -r0.w) + TTL;
    float ffT1 = fmaf(fr1, S2F, -r1.w) + TTL;
    float ffT2 = fmaf(fr2, S2F, -r2.w) + TTL;
    float ffT3 = fmaf(fr3, S2F, -r3.w) + TTL;

    float part = 0.f;
#pragma unroll 2
    for (int k = 0; k < 64; ++k) {
        int j = (k << 5) + lane;
        float4 q = tbl[j];
        float a0 = fmaf(r0.x, q.x, fmaf(r0.y, q.y, fmaf(r0.z, q.z, q.w)));
        float a1 = fmaf(r1.x, q.x, fmaf(r1.y, q.y, fmaf(r1.z, q.z, q.w)));
        float a2 = fmaf(r2.x, q.x, fmaf(r2.y, q.y, fmaf(r2.z, q.z, q.w)));
        float a3 = fmaf(r3.x, q.x, fmaf(r3.y, q.y, fmaf(r3.z, q.z, q.w)));
        float e0 = a0 + ffT0;
        float e1 = a1 + ffT1;
        float e2 = a2 + ffT2;
        float e3 = a3 + ffT3;
        float emax = fmaxf(fmaxf(e0, e1), fmaxf(e2, e3));
        if (__any_sync(0xffffffffu, emax > 0.f)) {
            float gj = gg[j];
            LROW(fr0, e0, gj)
            LROW(fr1, e1, gj)
            LROW(fr2, e2, gj)
            LROW(fr3, e3, gj)
        }
    }

    __shared__ float red[256];
    red[threadIdx.x] = part;
    __syncthreads();
#pragma unroll
    for (int o = 128; o; o >>= 1) {
        if (threadIdx.x < o) red[threadIdx.x] += red[threadIdx.x + o];
        __syncthreads();
    }
    if (threadIdx.x == 0) d_partials[blockIdx.x] = red[0];
}

__global__ void reduce_kernel(float* __restrict__ out) {
    __shared__ float red[256];
    float v = 0.f;
    for (int i = threadIdx.x; i < 512; i += 256) v += d_partials[i];
    red[threadIdx.x] = v;
    __syncthreads();
#pragma unroll
    for (int o = 128; o; o >>= 1) {
        if (threadIdx.x < o) red[threadIdx.x] += red[threadIdx.x + o];
        __syncthreads();
    }
    if (threadIdx.x == 0) out[0] = red[0] * 0.125f;
}

extern "C" void kernel_launch(void* const* d_in, const int* in_sizes, int n_in,
                              void* d_out, int out_size) {
    const float* preds = (const float*)d_in[0];
    const float* gts   = (const float*)d_in[1];
    float* out = (float*)d_out;

    prep_sort_kernel<<<BB * 2, 256>>>(preds, gts);
    for (int it = 0; it < 50; ++it) {
        half_kernel<<<BB * 64, 256>>>(0);
        half_kernel<<<BB * 64, 256>>>(1);
    }
    loss_kernel<<<BB * 64, 256>>>();
    reduce_kernel<<<1, 256>>>(out);
}

// round 5
// speedup vs baseline: 1.6707x; 1.6707x over previous
#include <cuda_runtime.h>
#include <math_constants.h>

// EMDLoss (Sinkhorn, eps=0.005, 50 iters), B=8, N=2048, dim=3.
// Morton-sorted sets + log2-domain factored cost. Iteration 0 runs a full
// online LSE (boot) that records each row's max; iterations 1..49 run a
// fixed-threshold kernel (fast) using the previous iteration's row max,
// so the MUFU/ex2 path only fires on genuine survivor chunks.

#define BB 8
#define NN 2048

static __device__ float4 d_P4[BB * NN];   // sorted (x,y,z, |p|^2*S2)
static __device__ float4 d_Q4[BB * NN];
static __device__ float  d_f[BB * NN];
static __device__ float  d_g[BB * NN];
static __device__ float  d_mf[BB * NN];   // row max (a-units) for f-update rows
static __device__ float  d_mg[BB * NN];   // row max for g-update rows
static __device__ float  d_partials[512];

__device__ __forceinline__ float ex2f_(float x) {
    float r; asm("ex2.approx.f32 %0, %1;" : "=f"(r) : "f"(x)); return r;
}
__device__ __forceinline__ float lg2f_(float x) {
    float r; asm("lg2.approx.f32 %0, %1;" : "=f"(r) : "f"(x)); return r;
}

#define S2F      288.5390081777927f      // 1/(eps*ln2)
#define S2X2     577.0780163555854f      // 2/(eps*ln2)
#define EPSLN2   0.0034657359027997f     // eps*ln2
#define EPSLOGMU (-0.03812309493079699f) // eps * (-ln N)
#define TT       25.0f                   // truncation window (log2)
#define SLACK    12.0f                   // allowed inter-iteration max drift
#define TTL      33.0f                   // loss truncation (log2)

// ---------------------------------------------------------------------------
// Morton-sort each (batch, set) with an in-smem bitonic sort.
__global__ void __launch_bounds__(256) prep_sort_kernel(
    const float* __restrict__ preds, const float* __restrict__ gts) {
    int blk = blockIdx.x;
    int b = blk >> 1;
    int set = blk & 1;
    const float* src = set ? gts : preds;
    float4* dst = set ? d_Q4 : d_P4;
    float*  pot = set ? d_g  : d_f;
    int off = b * NN;

    __shared__ unsigned skey[NN];

    for (int i = threadIdx.x; i < NN; i += 256) {
        const float* p = src + (off + i) * 3;
        float x = p[0], y = p[1], z = p[2];
        int ux = (int)floorf((x + 4.f) * 4.f); ux = min(31, max(0, ux));
        int uy = (int)floorf((y + 4.f) * 4.f); uy = min(31, max(0, uy));
        int uz = (int)floorf((z + 4.f) * 4.f); uz = min(31, max(0, uz));
        unsigned key = 0;
#pragma unroll
        for (int bit = 0; bit < 5; ++bit) {
            key |= (((unsigned)ux >> bit) & 1u) << (3 * bit + 2);
            key |= (((unsigned)uy >> bit) & 1u) << (3 * bit + 1);
            key |= (((unsigned)uz >> bit) & 1u) << (3 * bit + 0);
        }
        skey[i] = (key << 11) | (unsigned)i;
    }
    __syncthreads();

    for (int k = 2; k <= NN; k <<= 1) {
        for (int j = k >> 1; j > 0; j >>= 1) {
            for (int i = threadIdx.x; i < NN; i += 256) {
                int l = i ^ j;
                if (l > i) {
                    unsigned a = skey[i], c = skey[l];
                    bool up = ((i & k) == 0);
                    if ((a > c) == up) { skey[i] = c; skey[l] = a; }
                }
            }
            __syncthreads();
        }
    }

    for (int i = threadIdx.x; i < NN; i += 256) {
        int si = (int)(skey[i] & 2047u);
        const float* p = src + (off + si) * 3;
        float x = p[0], y = p[1], z = p[2];
        dst[off + i] = make_float4(x, y, z, (x * x + y * y + z * z) * S2F);
        pot[off + i] = 0.f;
    }
}

// ---------------------------------------------------------------------------
#define MERGEROW(m, s, off)                                         \
    {                                                               \
        float mo = __shfl_xor_sync(0xffffffffu, m, off);            \
        float so = __shfl_xor_sync(0xffffffffu, s, off);            \
        float mn = fmaxf(m, mo);                                    \
        s = fmaf(so, ex2f_(mo - mn), s * ex2f_(m - mn));            \
        m = mn;                                                     \
    }

#define ROWUPD(m, s, mt, a, e)                                      \
    if (__any_sync(0xffffffffu, (e) > 0.f)) {                       \
        if (__any_sync(0xffffffffu, (a) > (m))) {                   \
            float c = fmaxf(m, a);                                  \
            c = fmaxf(c, __shfl_xor_sync(0xffffffffu, c, 16));      \
            c = fmaxf(c, __shfl_xor_sync(0xffffffffu, c, 8));       \
            c = fmaxf(c, __shfl_xor_sync(0xffffffffu, c, 4));       \
            c = fmaxf(c, __shfl_xor_sync(0xffffffffu, c, 2));       \
            c = fmaxf(c, __shfl_xor_sync(0xffffffffu, c, 1));       \
            s = fmaf(s, ex2f_(m - c), ex2f_((a) - c));              \
            m = c; mt = c - TT;                                     \
        } else {                                                    \
            s += ex2f_((a) - m);                                    \
        }                                                           \
    }

// Boot half-update (iteration 0): full online LSE, stores row max.
__global__ void __launch_bounds__(256) half_boot(int dir) {
    int blk = blockIdx.x;
    int b = blk >> 6;
    int chunk = blk & 63;

    const float4* R4  = dir ? d_Q4 : d_P4;
    const float4* D4  = dir ? d_P4 : d_Q4;
    const float*  pin = dir ? d_f  : d_g;
    float*        pout = dir ? d_g : d_f;
    float*        mout = dir ? d_mg : d_mf;

    __shared__ float4 tbl[NN];
    {
        const float4* Db = D4 + b * NN;
        const float*  pb = pin + b * NN;
        for (int j = threadIdx.x; j < NN; j += 256) {
            float4 q = Db[j];
            float4 t;
            t.x = q.x * S2X2;
            t.y = q.y * S2X2;
            t.z = q.z * S2X2;
            t.w = fmaf(pb[j], S2F, -q.w);
            tbl[j] = t;
        }
    }
    __syncthreads();

    int warp = threadIdx.x >> 5;
    int lane = threadIdx.x & 31;
    int row0 = b * NN + chunk * 32 + warp * 4;

    float4 r0 = R4[row0 + 0];
    float4 r1 = R4[row0 + 1];
    float4 r2 = R4[row0 + 2];
    float4 r3 = R4[row0 + 3];

    const float NEGINF = -CUDART_INF_F;
    float m0 = NEGINF, m1 = NEGINF, m2 = NEGINF, m3 = NEGINF;
    float s0 = 0.f, s1 = 0.f, s2 = 0.f, s3 = 0.f;
    float mt0 = NEGINF, mt1 = NEGINF, mt2 = NEGINF, mt3 = NEGINF;

#pragma unroll 2
    for (int k = 0; k < 64; ++k) {
        float4 q = tbl[(k << 5) + lane];
        float a0 = fmaf(r0.x, q.x, fmaf(r0.y, q.y, fmaf(r0.z, q.z, q.w)));
        float a1 = fmaf(r1.x, q.x, fmaf(r1.y, q.y, fmaf(r1.z, q.z, q.w)));
        float a2 = fmaf(r2.x, q.x, fmaf(r2.y, q.y, fmaf(r2.z, q.z, q.w)));
        float a3 = fmaf(r3.x, q.x, fmaf(r3.y, q.y, fmaf(r3.z, q.z, q.w)));
        float e0 = a0 - mt0;
        float e1 = a1 - mt1;
        float e2 = a2 - mt2;
        float e3 = a3 - mt3;
        float emax = fmaxf(fmaxf(e0, e1), fmaxf(e2, e3));
        if (__any_sync(0xffffffffu, emax > 0.f)) {
            ROWUPD(m0, s0, mt0, a0, e0)
            ROWUPD(m1, s1, mt1, a1, e1)
            ROWUPD(m2, s2, mt2, a2, e2)
            ROWUPD(m3, s3, mt3, a3, e3)
        }
    }

#pragma unroll
    for (int off = 16; off; off >>= 1) {
        MERGEROW(m0, s0, off);
        MERGEROW(m1, s1, off);
        MERGEROW(m2, s2, off);
        MERGEROW(m3, s3, off);
    }

    if (lane == 0) {
        pout[row0 + 0] = fmaf(-EPSLN2, (-r0.w) + m0 + lg2f_(s0), EPSLOGMU);
        pout[row0 + 1] = fmaf(-EPSLN2, (-r1.w) + m1 + lg2f_(s1), EPSLOGMU);
        pout[row0 + 2] = fmaf(-EPSLN2, (-r2.w) + m2 + lg2f_(s2), EPSLOGMU);
        pout[row0 + 3] = fmaf(-EPSLN2, (-r3.w) + m3 + lg2f_(s3), EPSLOGMU);
        mout[row0 + 0] = m0;
        mout[row0 + 1] = m1;
        mout[row0 + 2] = m2;
        mout[row0 + 3] = m3;
    }
}

// Fast half-update: fixed threshold muT = m_prev - SLACK - TT. Tracks exact
// new row max; ex2 only on survivor steps.
__global__ void __launch_bounds__(256) half_fast(int dir) {
    int blk = blockIdx.x;
    int b = blk >> 6;
    int chunk = blk & 63;

    const float4* R4  = dir ? d_Q4 : d_P4;
    const float4* D4  = dir ? d_P4 : d_Q4;
    const float*  pin = dir ? d_f  : d_g;
    float*        pout = dir ? d_g : d_f;
    float*        marr = dir ? d_mg : d_mf;

    __shared__ float4 tbl[NN];
    {
        const float4* Db = D4 + b * NN;
        const float*  pb = pin + b * NN;
        for (int j = threadIdx.x; j < NN; j += 256) {
            float4 q = Db[j];
            float4 t;
            t.x = q.x * S2X2;
            t.y = q.y * S2X2;
            t.z = q.z * S2X2;
            t.w = fmaf(pb[j], S2F, -q.w);
            tbl[j] = t;
        }
    }
    __syncthreads();

    int warp = threadIdx.x >> 5;
    int lane = threadIdx.x & 31;
    int row0 = b * NN + chunk * 32 + warp * 4;

    float4 r0 = R4[row0 + 0];
    float4 r1 = R4[row0 + 1];
    float4 r2 = R4[row0 + 2];
    float4 r3 = R4[row0 + 3];

    float muT0 = marr[row0 + 0] - (SLACK + TT);
    float muT1 = marr[row0 + 1] - (SLACK + TT);
    float muT2 = marr[row0 + 2] - (SLACK + TT);
    float muT3 = marr[row0 + 3] - (SLACK + TT);

    const float NEGINF = -CUDART_INF_F;
    float s0 = 0.f, s1 = 0.f, s2 = 0.f, s3 = 0.f;
    float mx0 = NEGINF, mx1 = NEGINF, mx2 = NEGINF, mx3 = NEGINF;

#pragma unroll 2
    for (int k = 0; k < 64; ++k) {
        float4 q = tbl[(k << 5) + lane];
        float a0 = fmaf(r0.x, q.x, fmaf(r0.y, q.y, fmaf(r0.z, q.z, q.w)));
        float a1 = fmaf(r1.x, q.x, fmaf(r1.y, q.y, fmaf(r1.z, q.z, q.w)));
        float a2 = fmaf(r2.x, q.x, fmaf(r2.y, q.y, fmaf(r2.z, q.z, q.w)));
        float a3 = fmaf(r3.x, q.x, fmaf(r3.y, q.y, fmaf(r3.z, q.z, q.w)));
        float e0 = a0 - muT0;
        float e1 = a1 - muT1;
        float e2 = a2 - muT2;
        float e3 = a3 - muT3;
        mx0 = fmaxf(mx0, a0);
        mx1 = fmaxf(mx1, a1);
        mx2 = fmaxf(mx2, a2);
        mx3 = fmaxf(mx3, a3);
        float emax = fmaxf(fmaxf(e0, e1), fmaxf(e2, e3));
        if (__any_sync(0xffffffffu, emax > 0.f)) {
            s0 += ex2f_(e0);   // e <= 0 underflows harmlessly
            s1 += ex2f_(e1);
            s2 += ex2f_(e2);
            s3 += ex2f_(e3);
        }
    }

#pragma unroll
    for (int off = 16; off; off >>= 1) {
        s0 += __shfl_xor_sync(0xffffffffu, s0, off);
        s1 += __shfl_xor_sync(0xffffffffu, s1, off);
        s2 += __shfl_xor_sync(0xffffffffu, s2, off);
        s3 += __shfl_xor_sync(0xffffffffu, s3, off);
        mx0 = fmaxf(mx0, __shfl_xor_sync(0xffffffffu, mx0, off));
        mx1 = fmaxf(mx1, __shfl_xor_sync(0xffffffffu, mx1, off));
        mx2 = fmaxf(mx2, __shfl_xor_sync(0xffffffffu, mx2, off));
        mx3 = fmaxf(mx3, __shfl_xor_sync(0xffffffffu, mx3, off));
    }

    if (lane == 0) {
        pout[row0 + 0] = fmaf(-EPSLN2, (-r0.w) + muT0 + lg2f_(s0), EPSLOGMU);
        pout[row0 + 1] = fmaf(-EPSLN2, (-r1.w) + muT1 + lg2f_(s1), EPSLOGMU);
        pout[row0 + 2] = fmaf(-EPSLN2, (-r2.w) + muT2 + lg2f_(s2), EPSLOGMU);
        pout[row0 + 3] = fmaf(-EPSLN2, (-r3.w) + muT3 + lg2f_(s3), EPSLOGMU);
        marr[row0 + 0] = mx0;
        marr[row0 + 1] = mx1;
        marr[row0 + 2] = mx2;
        marr[row0 + 3] = mx3;
    }
}

// ---------------------------------------------------------------------------
#define LROW(fr, e, gj)                                             \
    if (__any_sync(0xffffffffu, (e) > 0.f)) {                       \
        float arg = (e) - TTL;                                      \
        float C = fmaf(-EPSLN2, arg, (fr) + (gj));                  \
        part = fmaf(ex2f_(arg), C, part);                           \
    }

__global__ void __launch_bounds__(256) loss_kernel() {
    int blk = blockIdx.x;
    int b = blk >> 6;
    int chunk = blk & 63;

    __shared__ float4 tbl[NN];
    __shared__ float  gg[NN];
    {
        const float4* Db = d_Q4 + b * NN;
        const float*  pb = d_g + b * NN;
        for (int j = threadIdx.x; j < NN; j += 256) {
            float4 q = Db[j];
            float gj = pb[j];
            float4 t;
            t.x = q.x * S2X2;
            t.y = q.y * S2X2;
            t.z = q.z * S2X2;
            t.w = fmaf(gj, S2F, -q.w);
            tbl[j] = t;
            gg[j] = gj;
        }
    }
    __syncthreads();

    int warp = threadIdx.x >> 5;
    int lane = threadIdx.x & 31;
    int row0 = b * NN + chunk * 32 + warp * 4;

    float4 r0 = d_P4[row0 + 0];
    float4 r1 = d_P4[row0 + 1];
    float4 r2 = d_P4[row0 + 2];
    float4 r3 = d_P4[row0 + 3];
    float fr0 = d_f[row0 + 0], fr1 = d_f[row0 + 1];
    float fr2 = d_f[row0 + 2], fr3 = d_f[row0 + 3];
    float ffT0 = fmaf(fr0, S2F, -r0.w) + TTL;
    float ffT1 = fmaf(fr1, S2F, -r1.w) + TTL;
    float ffT2 = fmaf(fr2, S2F, -r2.w) + TTL;
    float ffT3 = fmaf(fr3, S2F, -r3.w) + TTL;

    float part = 0.f;
#pragma unroll 2
    for (int k = 0; k < 64; ++k) {
        int j = (k << 5) + lane;
        float4 q = tbl[j];
        float a0 = fmaf(r0.x, q.x, fmaf(r0.y, q.y, fmaf(r0.z, q.z, q.w)));
        float a1 = fmaf(r1.x, q.x, fmaf(r1.y, q.y, fmaf(r1.z, q.z, q.w)));
        float a2 = fmaf(r2.x, q.x, fmaf(r2.y, q.y, fmaf(r2.z, q.z, q.w)));
        float a3 = fmaf(r3.x, q.x, fmaf(r3.y, q.y, fmaf(r3.z, q.z, q.w)));
        float e0 = a0 + ffT0;
        float e1 = a1 + ffT1;
        float e2 = a2 + ffT2;
        float e3 = a3 + ffT3;
        float emax = fmaxf(fmaxf(e0, e1), fmaxf(e2, e3));
        if (__any_sync(0xffffffffu, emax > 0.f)) {
            float gj = gg[j];
            LROW(fr0, e0, gj)
            LROW(fr1, e1, gj)
            LROW(fr2, e2, gj)
            LROW(fr3, e3, gj)
        }
    }

    __shared__ float red[256];
    red[threadIdx.x] = part;
    __syncthreads();
#pragma unroll
    for (int o = 128; o; o >>= 1) {
        if (threadIdx.x < o) red[threadIdx.x] += red[threadIdx.x + o];
        __syncthreads();
    }
    if (threadIdx.x == 0) d_partials[blockIdx.x] = red[0];
}

__global__ void reduce_kernel(float* __restrict__ out) {
    __shared__ float red[256];
    float v = 0.f;
    for (int i = threadIdx.x; i < 512; i += 256) v += d_partials[i];
    red[threadIdx.x] = v;
    __syncthreads();
#pragma unroll
    for (int o = 128; o; o >>= 1) {
        if (threadIdx.x < o) red[threadIdx.x] += red[threadIdx.x + o];
        __syncthreads();
    }
    if (threadIdx.x == 0) out[0] = red[0] * 0.125f;
}

extern "C" void kernel_launch(void* const* d_in, const int* in_sizes, int n_in,
                              void* d_out, int out_size) {
    const float* preds = (const float*)d_in[0];
    const float* gts   = (const float*)d_in[1];
    float* out = (float*)d_out;

    prep_sort_kernel<<<BB * 2, 256>>>(preds, gts);
    half_boot<<<BB * 64, 256>>>(0);
    half_boot<<<BB * 64, 256>>>(1);
    for (int it = 1; it < 50; ++it) {
        half_fast<<<BB * 64, 256>>>(0);
        half_fast<<<BB * 64, 256>>>(1);
    }
    loss_kernel<<<BB * 64, 256>>>();
    reduce_kernel<<<1, 256>>>(out);
}